// round 4
// baseline (speedup 1.0000x reference)
#include <cuda_runtime.h>
#include <math.h>

#define N       1024
#define NN      (N * N)
#define NN4     (NN / 4)
#define RESTART 16
#define NV      17
#define K2C     0.3f
#define ACOEF   (4.0f + K2C)
#define EPSF    1e-12f
#define TPB     256
#define NBLK    1024             /* NBLK*TPB == NN4 exactly */
#define NCYC    4
#define NPART   17               /* rows 0..15 = dots, row 16 = norm */

// ---------------- device scratch (allocations forbidden) --------------------
__device__ float4 g_P[NV][NN4];   // unnormalized basis; P[16] never materialized
__device__ float4 g_zA[NN4];      // z' ping-pong
__device__ float4 g_zB[NN4];
__device__ float4 g_x[NN4];
__device__ float  g_part[NPART][NBLK];
__device__ float  g_sig[NV];          // sigma_k = 1/(||P[k]||+eps)
__device__ float  g_hp[NV];           // previous step raw dots <P[k], z'>
__device__ float  g_e[NV];            // combo coeffs for next P
__device__ float  g_ew;               // combo coeff on z'
__device__ float  g_Q[NV * NV];       // <P[k], P[m]>
__device__ float  g_Hm[NV * RESTART]; // zeros below subdiag persist
__device__ float  g_y[RESTART];       // y_k * sigma_k (pre-scaled)
__device__ float  g_beta;
__device__ unsigned g_cnt;

// ---------------- helpers ----------------------------------------------------
struct Off { int c, u, d, l, r; };

__device__ __forceinline__ Off mkoff(int idx) {
    Off o;
    int row = idx >> 8, c4 = idx & 255;
    o.c = idx;
    o.u = (((row - 1) & (N - 1)) << 8) | c4;
    o.d = (((row + 1) & (N - 1)) << 8) | c4;
    int rb = row << 10;
    o.l = rb | (((c4 << 2) - 1) & (N - 1));
    o.r = rb | (((c4 << 2) + 4) & (N - 1));
    return o;
}

__device__ __forceinline__ void loadCN(const float4* __restrict__ u4, const Off& o,
                                       float4& C, float4& NS) {
    C = u4[o.c];
    float4 U = u4[o.u], D = u4[o.d];
    const float* uf = (const float*)u4;
    float L = uf[o.l], R = uf[o.r];
    NS.x = L   + C.y + U.x + D.x;
    NS.y = C.x + C.z + U.y + D.y;
    NS.z = C.y + C.w + U.z + D.z;
    NS.w = C.z + R   + U.w + D.w;
}

__device__ __forceinline__ float dot4(float4 a, float4 b) {
    return a.x * b.x + a.y * b.y + a.z * b.z + a.w * b.w;
}

__device__ __forceinline__ float warpSum(float v) {
#pragma unroll
    for (int o = 16; o > 0; o >>= 1) v += __shfl_down_sync(0xffffffffu, v, o);
    return v;
}

__device__ __forceinline__ void blockPartials(const float* acc, int nk, bool withNorm) {
    __shared__ float sred[NPART][TPB / 32];
    int lane = threadIdx.x & 31, warp = threadIdx.x >> 5;
#pragma unroll
    for (int k = 0; k < RESTART; k++)
        if (k < nk) {
            float v = warpSum(acc[k]);
            if (lane == 0) sred[k][warp] = v;
        }
    if (withNorm) {
        float v = warpSum(acc[16]);
        if (lane == 0) sred[16][warp] = v;
    }
    __syncthreads();
    int t = threadIdx.x;
    if (t < nk || (withNorm && t == 16)) {
        float s = 0.f;
#pragma unroll
        for (int w = 0; w < TPB / 32; w++) s += sred[t][w];
        g_part[t][blockIdx.x] = s;
        __threadfence();
    }
    __syncthreads();
}

__device__ __forceinline__ bool isLastBlock() {
    __shared__ unsigned s_last;
    if (threadIdx.x == 0)
        s_last = (atomicAdd(&g_cnt, 1u) == (unsigned)(gridDim.x - 1));
    __syncthreads();
    return s_last != 0;
}

__device__ __forceinline__ void finalTotals(float* s_tot, int nk, bool withNorm) {
    int warp = threadIdx.x >> 5, lane = threadIdx.x & 31;
    for (int k = warp; k < NPART; k += TPB / 32) {
        bool active = (k < nk) || (withNorm && k == 16);
        if (!active) continue;
        float s = 0.f;
        for (int b = lane; b < NBLK; b += 32) s += g_part[k][b];
        s = warpSum(s);
        if (lane == 0) s_tot[k] = s;
    }
    __syncthreads();
}

// ---------------- kernels ------------------------------------------------------
__global__ void __launch_bounds__(TPB) k_init(const float4* __restrict__ guess) {
    int i = blockIdx.x * TPB + threadIdx.x;
    g_x[i] = guess[i];
}

// P[0] = b - A(x)   (no reduction; beta computed by k_arn(0))
__global__ void __launch_bounds__(TPB, 7) k_resid(const float4* __restrict__ b) {
    int i = blockIdx.x * TPB + threadIdx.x;
    Off o = mkoff(i);
    float4 c, n;
    loadCN(g_x, o, c, n);
    float4 bb = b[i];
    float4 r;
    r.x = bb.x - (ACOEF * c.x - n.x);
    r.y = bb.y - (ACOEF * c.y - n.y);
    r.z = bb.z - (ACOEF * c.z - n.z);
    r.w = bb.w - (ACOEF * c.w - n.w);
    g_P[0][i] = r;
}

// One Arnoldi step, single sweep:
//   p    = ew*zin - sum_{k<j} e_k P[k]          (footprint, = unnormalized V[j])
//   P[j] = p (j>0); zout = A(p)
//   reduce: h'_k = <P[k], zout> (k<j), h'_j = <p, zout>, nrm = <p,p>
// Epilogue (last block): hn, sigma_j, Hm subdiag, Q column via recurrence,
//   h2 = h - Gh, c = h+h2, Hm[:,j] = c, next combo coeffs e/ew.
__global__ void __launch_bounds__(TPB, 7) k_arn(int j) {
    const float4* __restrict__ zin =
        (j == 0) ? g_P[0] : ((j & 1) ? g_zA : g_zB);
    float4* __restrict__ zout = (j & 1) ? g_zB : g_zA;

    __shared__ float es[RESTART];
    if (threadIdx.x < RESTART) es[threadIdx.x] = g_e[threadIdx.x];
    __syncthreads();
    float ew = (j == 0) ? 1.0f : g_ew;

    int i = blockIdx.x * TPB + threadIdx.x;
    Off o = mkoff(i);

    float4 pc, pn;
    {
        float4 C, NS;
        loadCN(zin, o, C, NS);
        pc.x = ew * C.x;  pc.y = ew * C.y;  pc.z = ew * C.z;  pc.w = ew * C.w;
        pn.x = ew * NS.x; pn.y = ew * NS.y; pn.z = ew * NS.z; pn.w = ew * NS.w;
    }
#pragma unroll
    for (int k = 0; k < RESTART; k++)
        if (k < j) {
            float e = es[k];
            float4 C, NS;
            loadCN(g_P[k], o, C, NS);
            pc.x -= e * C.x;  pc.y -= e * C.y;  pc.z -= e * C.z;  pc.w -= e * C.w;
            pn.x -= e * NS.x; pn.y -= e * NS.y; pn.z -= e * NS.z; pn.w -= e * NS.w;
        }

    if (j > 0) g_P[j][i] = pc;

    float4 z;
    z.x = ACOEF * pc.x - pn.x;
    z.y = ACOEF * pc.y - pn.y;
    z.z = ACOEF * pc.z - pn.z;
    z.w = ACOEF * pc.w - pn.w;
    zout[i] = z;

    float acc[NPART];
#pragma unroll
    for (int k = 0; k < NPART; k++) acc[k] = 0.f;
#pragma unroll
    for (int k = 0; k < RESTART; k++) {
        if (k < j)       acc[k] = dot4(g_P[k][i], z);   // center reload: L1 hit
        else if (k == j) acc[k] = dot4(pc, z);
    }
    acc[16] = dot4(pc, pc);

    blockPartials(acc, j + 1, true);
    if (isLastBlock()) {
        __shared__ float tot[NPART];
        finalTotals(tot, j + 1, true);
        __shared__ float s_sig[NV], s_h[NV];
        int t = threadIdx.x;
        if (t == 0) {
            float hn = sqrtf(tot[16]);
            g_sig[j] = 1.0f / (hn + EPSF);
            if (j > 0) g_Hm[j * RESTART + (j - 1)] = hn;
            else       g_beta = hn;
            g_Q[j * NV + j] = tot[16];
        }
        __syncthreads();
        if (t <= j) s_sig[t] = g_sig[t];
        __syncthreads();
        // Q column j via recurrence: <P[t],P[j]> = ew*hp[t] - sum e_m Q[t][m]
        if (t < j) {
            float q = ew * g_hp[t];
            for (int m = 0; m < j; m++) q -= es[m] * g_Q[t * NV + m];
            g_Q[t * NV + j] = q;
            g_Q[j * NV + t] = q;
        }
        if (t <= j) {
            s_h[t]  = s_sig[t] * s_sig[j] * tot[t];  // true h_k
            g_hp[t] = tot[t];
        }
        __syncthreads();
        if (t <= j) {
            float gh = 0.f;
            for (int m = 0; m <= j; m++)
                gh += s_sig[t] * s_sig[m] * g_Q[t * NV + m] * s_h[m];
            float c = 2.0f * s_h[t] - gh;          // h + h2,  h2 = h - Gh
            g_Hm[t * RESTART + j] = c;
            g_e[t] = c * s_sig[t];
        }
        if (t == 0) { g_ew = s_sig[j]; g_cnt = 0; }
    }
}

// ||P[16]||^2 (centers only) -> Hm[16][15]; then 16x16 solve; y pre-scaled by sigma
__global__ void __launch_bounds__(TPB, 7) k_fin() {
    __shared__ float es[RESTART];
    if (threadIdx.x < RESTART) es[threadIdx.x] = g_e[threadIdx.x];
    __syncthreads();
    float ew = g_ew;

    int i = blockIdx.x * TPB + threadIdx.x;
    float4 zc = g_zB[i];   // z' of step 15 (15 is odd -> wrote zB)
    float4 p;
    p.x = ew * zc.x; p.y = ew * zc.y; p.z = ew * zc.z; p.w = ew * zc.w;
#pragma unroll
    for (int k = 0; k < RESTART; k++) {
        float e = es[k];
        float4 v = g_P[k][i];
        p.x -= e * v.x; p.y -= e * v.y; p.z -= e * v.z; p.w -= e * v.w;
    }
    float acc[NPART];
    acc[16] = dot4(p, p);

    blockPartials(acc, 0, true);
    if (isLastBlock()) {
        __shared__ float tot[NPART];
        finalTotals(tot, 0, true);
        int t = threadIdx.x;
        if (t == 0) g_Hm[16 * RESTART + 15] = sqrtf(tot[16]);
        __syncthreads();

        __shared__ float sG[RESTART][RESTART], sf[RESTART], rhs[RESTART];
        {
            int a = t >> 4, b = t & 15;      // 256 threads = 16x16
            float su = 0.f;
            for (int r = 0; r < NV; r++)
                su += g_Hm[r * RESTART + a] * g_Hm[r * RESTART + b];
            sG[a][b] = su + ((a == b) ? EPSF : 0.f);
        }
        if (t < RESTART) rhs[t] = g_Hm[t] * g_beta;   // Hm row 0
        __syncthreads();

        for (int p2 = 0; p2 < RESTART; p2++) {
            if (t > p2 && t < RESTART) sf[t] = sG[t][p2] / sG[p2][p2];
            __syncthreads();
            int r = t >> 4, c = t & 15;
            if (r > p2 && c > p2) sG[r][c] -= sf[r] * sG[p2][c];
            if (t > p2 && t < RESTART) rhs[t] -= sf[t] * rhs[p2];
            __syncthreads();
        }
        if (t == 0) {
            for (int p2 = RESTART - 1; p2 >= 0; p2--) {
                float su = rhs[p2];
                for (int c = p2 + 1; c < RESTART; c++) su -= sG[p2][c] * rhs[c];
                rhs[p2] = su / sG[p2][p2];
            }
        }
        __syncthreads();
        if (t < RESTART) g_y[t] = rhs[t] * g_sig[t];
        if (t == 0) g_cnt = 0;
    }
}

// x += sum_k y_k P[k]  (y pre-scaled by sigma); optionally emit
__global__ void __launch_bounds__(TPB, 7) k_xupd(float4* __restrict__ out) {
    __shared__ float ys[RESTART];
    if (threadIdx.x < RESTART) ys[threadIdx.x] = g_y[threadIdx.x];
    __syncthreads();
    int i = blockIdx.x * TPB + threadIdx.x;
    float4 s = g_x[i];
#pragma unroll
    for (int k = 0; k < RESTART; k++) {
        float y = ys[k];
        float4 v = g_P[k][i];
        s.x += y * v.x; s.y += y * v.y; s.z += y * v.z; s.w += y * v.w;
    }
    g_x[i] = s;
    if (out) out[i] = s;
}

// ---------------- host orchestration ----------------------------------------
extern "C" void kernel_launch(void* const* d_in, const int* in_sizes, int n_in,
                              void* d_out, int out_size) {
    (void)in_sizes; (void)n_in; (void)out_size;
    const float4* src   = (const float4*)d_in[0];
    const float4* guess = (const float4*)d_in[1];
    float4* out = (float4*)d_out;

    k_init<<<NBLK, TPB>>>(guess);

    for (int c = 0; c < NCYC; c++) {
        k_resid<<<NBLK, TPB>>>(src);
        for (int j = 0; j < RESTART; j++)
            k_arn<<<NBLK, TPB>>>(j);
        k_fin<<<NBLK, TPB>>>();
        k_xupd<<<NBLK, TPB>>>(c == NCYC - 1 ? out : nullptr);
    }
}